// round 6
// baseline (speedup 1.0000x reference)
#include <cuda_runtime.h>
#include <cstdint>
#include <cstddef>

#define TB   128   // batch
#define TT   512   // time steps
#define EE   256   // embedding dim
#define HH   256   // hidden dim
#define G4   1024  // 4*H gate width
#define VV   32000 // vocab
#define NCLS 32    // classes
#define NCTA 128   // persistent grid size (<=148 SMs -> co-resident guaranteed)

#define USTRIDE 260                       // padded k-stride (floats); 16B-aligned
#define SU_FLOATS   (128 * USTRIDE)       // 33,280 floats = 133,120 B
#define STOK_INTS   (16 * TT)             // 8,192 ints    =  32,768 B
#define DYN_BYTES   (SU_FLOATS * 4 + STOK_INTS * 4)   // 165,888 B

// ---- static device scratch (no allocations allowed) ----
__device__ float g_embW[(size_t)2 * VV * G4];   // [dir][V][4H]  = 262 MB
__device__ float g_hbuf[2 * 2 * TB * HH];       // [buf][dir][b][j] double-buffered h
__device__ int   g_flags[NCTA * 8];             // per-CTA barrier flags (padded)

__device__ __forceinline__ float sigm(float x) { return 1.0f / (1.0f + __expf(-x)); }

// packed fp32x2 FMA (FFMA2) — bit-exact 2x fp32, sm_100+ PTX
#define FMA_F32X2(d, a, b, c) \
    asm("fma.rn.f32x2 %0, %1, %2, %3;" : "=l"(d) : "l"(a), "l"(b), "l"(c))
#define UNPACK_F32X2(lo, hi, in) \
    asm("mov.b64 {%0, %1}, %2;" : "=f"(lo), "=f"(hi) : "l"(in))
#define PACK_DUP_F32X2(out, x) \
    asm("mov.b64 %0, {%1, %1};" : "=l"(out) : "r"(x))

// ============================================================================
// Kernel 1: embW[d][v][g] = sum_e emb[v][e] * W_d[e][g]
// grid (V/32, 4, 2), block 256. Tile: 32 v-rows x 256 g-cols, K=256.
// FFMA2 pairs over v; launch_bounds(256,4) for occupancy.
// ============================================================================
__global__ void __launch_bounds__(256, 4) k_embW(const float* __restrict__ emb,
                                                 const float* __restrict__ Wf,
                                                 const float* __restrict__ Wb)
{
    __shared__ float she[256][36];   // [e][v], v-contiguous, 16B-aligned rows
    const int v0  = blockIdx.x * 32;
    const int gt  = blockIdx.y;
    const int d   = blockIdx.z;
    const int tid = threadIdx.x;
    const float* __restrict__ W = d ? Wb : Wf;

    for (int idx = tid; idx < 32 * 256; idx += 256) {
        int vl = idx >> 8, e = idx & 255;
        she[e][vl] = emb[(size_t)(v0 + vl) * EE + e];   // coalesced over e
    }
    __syncthreads();

    const int g = gt * 256 + tid;
    unsigned long long acc2[16];     // lanes = (v=2q, v=2q+1)
#pragma unroll
    for (int q = 0; q < 16; ++q) acc2[q] = 0ull;

    const float* __restrict__ Wg = W + g;
#pragma unroll 4
    for (int e = 0; e < 256; ++e) {
        float w = Wg[(size_t)e * G4];                   // coalesced 128B/warp
        unsigned long long w2;
        PACK_DUP_F32X2(w2, __float_as_int(w));
#pragma unroll
        for (int p = 0; p < 8; ++p) {
            ulonglong2 a = *(const ulonglong2*)&she[e][p * 4]; // broadcast LDS.128
            FMA_F32X2(acc2[2 * p],     a.x, w2, acc2[2 * p]);
            FMA_F32X2(acc2[2 * p + 1], a.y, w2, acc2[2 * p + 1]);
        }
    }
    size_t base = ((size_t)d * VV + v0) * G4 + g;
#pragma unroll
    for (int q = 0; q < 16; ++q) {
        float lo, hi;
        UNPACK_F32X2(lo, hi, acc2[q]);
        g_embW[base + (size_t)(2 * q)     * G4] = lo;
        g_embW[base + (size_t)(2 * q + 1) * G4] = hi;
    }
}

// ============================================================================
// Kernel 2: persistent bidirectional LSTM recurrence.
// 128 CTAs x 512 threads. CTA = (dir, b-tile of 16, 32 strided gate cols).
// k-split: thread halves share each dot product (4 warps/SMSP latency hiding).
// U staged once to smem [col][k]; tokens staged once; xw prefetched one step
// ahead; c-state lives in a register; flag-array grid barrier (no atomics).
// ============================================================================
__global__ void __launch_bounds__(512, 1) k_lstm(const void* __restrict__ tokens_raw,
                                                 const float* __restrict__ Uf,
                                                 const float* __restrict__ bf,
                                                 const float* __restrict__ Ub,
                                                 const float* __restrict__ bb)
{
    extern __shared__ char dyn[];
    float* __restrict__ sU   = (float*)dyn;                     // [128][USTRIDE]
    int*   __restrict__ stok = (int*)(dyn + SU_FLOATS * 4);     // [16][TT]

    __shared__ float sh_h[16][USTRIDE];   // [b][k] h tile, k-contiguous
    __shared__ float sz[2][16][128];      // partial z per k-half [kh][b][cl]

    const int id  = blockIdx.x;
    const int jt  = id & 7;
    const int bt  = (id >> 3) & 7;
    const int d   = id >> 6;
    const int tid = threadIdx.x;

    const float* __restrict__ U   = d ? Ub : Uf;
    const float* __restrict__ bia = d ? bb : bf;

    const int b0      = bt * 16;
    const int colbase = jt * 32;
    // ---- GEMM-phase mapping ----
    const int kh     = tid >> 8;            // k-half 0/1
    const int t8     = tid & 255;
    const int cl     = t8 & 127;            // gate-local column 0..127
    const int bh2    = t8 >> 7;             // batch half 0/1
    const int col    = colbase + (cl & 31) + ((cl >> 5) << 8);
    const int bloc0  = bh2 * 8;
    const int khbase = kh * 128;
    // ---- gate-phase mapping (one cell per thread) ----
    const int gbl = tid >> 5;               // 0..15 local batch row
    const int gjj = tid & 31;               // 0..31 local hidden col

    // ---- runtime token dtype probe: int64 high words are all zero ----
    const int*       __restrict__ t32 = (const int*)tokens_raw;
    const long long* __restrict__ t64 = (const long long*)tokens_raw;
    int probe = 0;
#pragma unroll
    for (int i = 1; i < 64; i += 2) probe |= t32[i];
    const bool tok32 = (probe != 0);

    // ---- one-time stages ----
    // U transposed: sU[cl][k] = U[k][col]; (cl,kh,bh2) covers 64 k each
    {
        const int k0 = khbase + bh2 * 64;
        for (int k = k0; k < k0 + 64; ++k)
            sU[cl * USTRIDE + k] = U[(size_t)k * G4 + col];   // coalesced over cl
    }
    // tokens for this CTA's 16 batch rows
    for (int idx = tid; idx < STOK_INTS; idx += 512) {
        int bl = idx >> 9, t = idx & (TT - 1);
        stok[idx] = tok32 ? t32[(b0 + bl) * TT + t]
                          : (int)t64[(b0 + bl) * TT + t];
    }
    const int base = *(volatile int*)&g_flags[id * 8];  // uniform at launch
    __syncthreads();

    // per-gate-thread constants / state
    float bq[4];
#pragma unroll
    for (int q = 0; q < 4; ++q) bq[q] = bia[colbase + gjj + q * 256];
    float creg = 0.f;

    // prefetch xw for step 0
    float xnext[4];
    {
        const int ts0 = d ? (TT - 1) : 0;
        int tk = stok[gbl * TT + ts0];
        size_t gb = ((size_t)d * VV + tk) * G4 + colbase + gjj;
#pragma unroll
        for (int q = 0; q < 4; ++q) xnext[q] = g_embW[gb + q * 256];
    }

    const float* __restrict__ Urow = &sU[cl * USTRIDE + khbase];

    for (int s = 0; s < TT; ++s) {
        unsigned long long acc2[8];
#pragma unroll
        for (int r = 0; r < 8; ++r) acc2[r] = 0ull;

        if (s > 0) {   // h_0 = 0 -> skip recurrent GEMM at step 0
            const int rb = s & 1;   // step s-1 wrote buffer s&1
            const float* __restrict__ hsrc =
                g_hbuf + ((size_t)(rb * 2 + d) * TB + b0) * HH;
#pragma unroll
            for (int i = 0; i < 2; ++i) {            // 1024 float4 slots
                int idx = tid + i * 512;
                int bl = idx >> 6, kq = idx & 63;
                *(float4*)&sh_h[bl][kq * 4] =
                    *(const float4*)&hsrc[bl * HH + kq * 4];
            }
            __syncthreads();

#pragma unroll 2
            for (int kc = 0; kc < 32; ++kc) {        // 4 k per chunk, half range
                ulonglong2 u = *(const ulonglong2*)(Urow + kc * 4);
#pragma unroll
                for (int r = 0; r < 8; ++r) {
                    ulonglong2 hv =
                        *(const ulonglong2*)&sh_h[bloc0 + r][khbase + kc * 4];
                    FMA_F32X2(acc2[r], hv.x, u.x, acc2[r]);
                    FMA_F32X2(acc2[r], hv.y, u.y, acc2[r]);
                }
            }
        }
        // write partial dot products
#pragma unroll
        for (int r = 0; r < 8; ++r) {
            float lo, hi;
            UNPACK_F32X2(lo, hi, acc2[r]);
            sz[kh][bloc0 + r][cl] = lo + hi;
        }
        __syncthreads();

        // ---- gate update: one cell per thread; c stays in a register ----
        {
            float zi = sz[0][gbl][gjj]       + sz[1][gbl][gjj]       + xnext[0] + bq[0];
            float zf = sz[0][gbl][32 + gjj]  + sz[1][gbl][32 + gjj]  + xnext[1] + bq[1];
            float zg = sz[0][gbl][64 + gjj]  + sz[1][gbl][64 + gjj]  + xnext[2] + bq[2];
            float zo = sz[0][gbl][96 + gjj]  + sz[1][gbl][96 + gjj]  + xnext[3] + bq[3];
            float cn = sigm(zf) * creg + sigm(zi) * tanhf(zg);
            float h  = sigm(zo) * tanhf(cn);
            creg = cn;
            g_hbuf[((size_t)(((s + 1) & 1) * 2 + d) * TB + (b0 + gbl)) * HH
                   + colbase + gjj] = h;
        }
        // prefetch xw for step s+1 (off the critical path, before barrier)
        if (s + 1 < TT) {
            const int ts1 = d ? (TT - 2 - s) : (s + 1);
            int tk = stok[gbl * TT + ts1];
            size_t gb = ((size_t)d * VV + tk) * G4 + colbase + gjj;
#pragma unroll
            for (int q = 0; q < 4; ++q) xnext[q] = g_embW[gb + q * 256];
        }
        __syncthreads();

        // ---- grid barrier: release flag, parallel poll (no atomics) ----
        if (tid == 0) {
            __threadfence();                         // release all CTA stores
            *(volatile int*)&g_flags[id * 8] = base + s + 1;
        }
        if (tid < NCTA) {
            const volatile int* f = &g_flags[tid * 8];
            const int target = base + s + 1;
            while (*f - target < 0) { }
            __threadfence();        // acquire + L1D invalidate (CCTL.IVALL)
        }
        __syncthreads();
    }
}

// ============================================================================
// Kernel 3: head. One block per batch row.
// h_cat[512] -> relu(dense 256) -> logits 32 -> softmax. Final h in buf 0.
// ============================================================================
__global__ void __launch_bounds__(256) k_head(const float* __restrict__ W1,
                                              const float* __restrict__ b1,
                                              const float* __restrict__ W2,
                                              const float* __restrict__ b2,
                                              float* __restrict__ out)
{
    __shared__ float sh[512];
    __shared__ float sy[256];
    __shared__ float red[8][33];
    const int b = blockIdx.x, tid = threadIdx.x;

    sh[tid]       = g_hbuf[((size_t)0 * TB + b) * HH + tid]; // fwd (buf0, dir0)
    sh[256 + tid] = g_hbuf[((size_t)1 * TB + b) * HH + tid]; // bwd (buf0, dir1)
    __syncthreads();

    float a = b1[tid];
    for (int k = 0; k < 512; ++k) a = fmaf(sh[k], W1[(size_t)k * HH + tid], a);
    sy[tid] = fmaxf(a, 0.f);
    __syncthreads();

    const int part = tid >> 5, c = tid & 31;
    float p = 0.f;
#pragma unroll
    for (int kk = 0; kk < 32; ++kk) {
        int k = part * 32 + kk;
        p = fmaf(sy[k], W2[(size_t)k * NCLS + c], p);
    }
    red[part][c] = p;
    __syncthreads();

    if (tid < 32) {
        float l = b2[tid];
#pragma unroll
        for (int q = 0; q < 8; ++q) l += red[q][tid];
        float m = l;
#pragma unroll
        for (int off = 16; off; off >>= 1)
            m = fmaxf(m, __shfl_xor_sync(0xffffffffu, m, off));
        float e = __expf(l - m);
        float ssum = e;
#pragma unroll
        for (int off = 16; off; off >>= 1)
            ssum += __shfl_xor_sync(0xffffffffu, ssum, off);
        out[b * NCLS + tid] = e / ssum;
    }
}

// ============================================================================
extern "C" void kernel_launch(void* const* d_in, const int* in_sizes, int n_in,
                              void* d_out, int out_size)
{
    const void*  tokens = d_in[0];
    const float* emb = (const float*)d_in[1];
    const float* Wf  = (const float*)d_in[2];
    const float* Uf  = (const float*)d_in[3];
    const float* bf  = (const float*)d_in[4];
    const float* Wb  = (const float*)d_in[5];
    const float* Ub  = (const float*)d_in[6];
    const float* bb  = (const float*)d_in[7];
    const float* W1  = (const float*)d_in[8];
    const float* b1  = (const float*)d_in[9];
    const float* W2  = (const float*)d_in[10];
    const float* b2  = (const float*)d_in[11];
    float* out = (float*)d_out;

    cudaFuncSetAttribute(k_lstm, cudaFuncAttributeMaxDynamicSharedMemorySize,
                         DYN_BYTES);

    k_embW<<<dim3(VV / 32, 4, 2), 256>>>(emb, Wf, Wb);
    k_lstm<<<NCTA, 512, DYN_BYTES>>>(tokens, Uf, bf, Ub, bb);
    k_head<<<TB, 256>>>(W1, b1, W2, b2, out);
}